// round 9
// baseline (speedup 1.0000x reference)
#include <cuda_runtime.h>
#include <cstdint>

// NativeSparseAttention: S=8192, B=16, E=128, fp32
// Persistent kernel, warp-level tf32 mma.sync (m16n8k8), 256 threads, 1 CTA/SM.
// R8: Wk/Wv fragments register-resident (128 regs/thr, loaded once);
//     P2 streams unnormalized E~; normalization folded into P3 epilogue.

#define S_TOTAL 8192

// strides (floats)
#define SX 136
#define SK 20
#define SV 136
#define SE 136
#define SWS 132   // W staging stride (startup only)

// smem offsets (floats)
#define OFF_X   0                          // 16 x SX        = 2176
#define OFF_K   2176                       // 128 x SK       = 2560
#define OFF_INV 4736                       // 128
#define OFF_V   4864                       // 128 x SV       = 17408
#define OFF_E   22272                      // 128 x SE       = 17408
#define SMEM_FLOATS 39680
#define SMEM_BYTES  (SMEM_FLOATS * 4)      // 158720
// startup W staging: Wk at OFF_V, Wv at OFF_V + 16896 (fits before SMEM end)
#define OFF_SCR OFF_V

__device__ __forceinline__ uint32_t f2t(float f) {
    uint32_t u; asm("cvt.rna.tf32.f32 %0, %1;" : "=r"(u) : "f"(f)); return u;
}
__device__ __forceinline__ float ex2f(float x) {
    float y; asm("ex2.approx.f32 %0, %1;" : "=f"(y) : "f"(x)); return y;
}
__device__ __forceinline__ void mma8(float* d, const uint32_t* a, const uint32_t* b) {
    asm volatile(
        "mma.sync.aligned.m16n8k8.row.col.f32.tf32.tf32.f32 "
        "{%0,%1,%2,%3}, {%4,%5,%6,%7}, {%8,%9}, {%0,%1,%2,%3};"
        : "+f"(d[0]), "+f"(d[1]), "+f"(d[2]), "+f"(d[3])
        : "r"(a[0]), "r"(a[1]), "r"(a[2]), "r"(a[3]), "r"(b[0]), "r"(b[1]));
}

__global__ __launch_bounds__(256, 1)
void nsa_mma(const float* __restrict__ x,
             const float* __restrict__ Wk,
             const float* __restrict__ bk,
             const float* __restrict__ Wv,
             const float* __restrict__ bv,
             float* __restrict__ out) {
    extern __shared__ float sm[];
    uint32_t* smu = reinterpret_cast<uint32_t*>(sm);

    const int t = threadIdx.x;
    const int wid = t >> 5;
    const int lid = t & 31;
    const int qr = lid >> 2;    // groupID 0..7
    const int qc = lid & 3;     // threadID-in-group 0..3
    const int ebk = wid * 16;   // warp's e-block base

    // ---- startup: stage W to scratch smem, extract per-warp A-fragments ----
    #pragma unroll
    for (int i = 0; i < 16; i++) {
        const int l = t + 256 * i;          // float4 index over 128x128
        const int r = l >> 5, c = (l & 31) * 4;
        float4 a = reinterpret_cast<const float4*>(Wk)[l];
        uint4 pa = { f2t(a.x), f2t(a.y), f2t(a.z), f2t(a.w) };
        *reinterpret_cast<uint4*>(&smu[OFF_SCR + r * SWS + c]) = pa;
        float4 b = reinterpret_cast<const float4*>(Wv)[l];
        uint4 pb = { f2t(b.x), f2t(b.y), f2t(b.z), f2t(b.w) };
        *reinterpret_cast<uint4*>(&smu[OFF_SCR + 16896 + r * SWS + c]) = pb;
    }
    __syncthreads();

    uint32_t wkf[16][4], wvf[16][4];
    #pragma unroll
    for (int kk = 0; kk < 16; kk++) {
        const int jb = kk * 8;
        wkf[kk][0] = smu[OFF_SCR + (ebk + qr) * SWS + jb + qc];
        wkf[kk][1] = smu[OFF_SCR + (ebk + qr + 8) * SWS + jb + qc];
        wkf[kk][2] = smu[OFF_SCR + (ebk + qr) * SWS + jb + qc + 4];
        wkf[kk][3] = smu[OFF_SCR + (ebk + qr + 8) * SWS + jb + qc + 4];
        wvf[kk][0] = smu[OFF_SCR + 16896 + (ebk + qr) * SWS + jb + qc];
        wvf[kk][1] = smu[OFF_SCR + 16896 + (ebk + qr + 8) * SWS + jb + qc];
        wvf[kk][2] = smu[OFF_SCR + 16896 + (ebk + qr) * SWS + jb + qc + 4];
        wvf[kk][3] = smu[OFF_SCR + 16896 + (ebk + qr + 8) * SWS + jb + qc + 4];
    }
    const float bk0 = __ldg(bk + ebk + qr), bk1 = __ldg(bk + ebk + qr + 8);
    const float bv0 = __ldg(bv + ebk + qr), bv1 = __ldg(bv + ebk + qr + 8);
    const float C2 = 0.015939678942f;       // log2(e)/sqrt(8192)
    __syncthreads();                        // scratch reads done before v reuse

    int s = blockIdx.x;
    float4 xr0, xr1;
    if (s < S_TOTAL) {
        const float4* xg = reinterpret_cast<const float4*>(x + (size_t)s * 2048);
        xr0 = xg[t]; xr1 = xg[t + 256];
    }

    while (s < S_TOTAL) {
        // ---- stage x (tf32) into [b][j] stride SX ----
        {
            const int b0i = t >> 5,         c0 = (t & 31) * 4;
            const int b1i = (t + 256) >> 5, c1 = ((t + 256) & 31) * 4;
            uint4 h;
            h.x = f2t(xr0.x); h.y = f2t(xr0.y); h.z = f2t(xr0.z); h.w = f2t(xr0.w);
            *reinterpret_cast<uint4*>(&smu[OFF_X + b0i * SX + c0]) = h;
            h.x = f2t(xr1.x); h.y = f2t(xr1.y); h.z = f2t(xr1.z); h.w = f2t(xr1.w);
            *reinterpret_cast<uint4*>(&smu[OFF_X + b1i * SX + c1]) = h;
        }
        __syncthreads();

        // ---- prefetch next x into regs ----
        const int snext = s + gridDim.x;
        if (snext < S_TOTAL) {
            const float4* xg = reinterpret_cast<const float4*>(x + (size_t)snext * 2048);
            xr0 = xg[t]; xr1 = xg[t + 256];
        }

        // ======== phase 1: kT = Wk@xT, vT = Wv@xT  (M=e16, N=b16, K=128) ========
        uint32_t xf[16][4];
        float kD[2][4] = {{0,0,0,0},{0,0,0,0}};
        float vD[2][4] = {{0,0,0,0},{0,0,0,0}};
        #pragma unroll
        for (int kk = 0; kk < 16; kk++) {
            const int jb = kk * 8;
            xf[kk][0] = smu[OFF_X + qr * SX + jb + qc];
            xf[kk][1] = smu[OFF_X + qr * SX + jb + qc + 4];
            xf[kk][2] = smu[OFF_X + (qr + 8) * SX + jb + qc];
            xf[kk][3] = smu[OFF_X + (qr + 8) * SX + jb + qc + 4];
            mma8(kD[0], wkf[kk], &xf[kk][0]); mma8(kD[1], wkf[kk], &xf[kk][2]);
            mma8(vD[0], wvf[kk], &xf[kk][0]); mma8(vD[1], wvf[kk], &xf[kk][2]);
        }
        // store k as [e][b] (stride SK), v as [b][f] (stride SV), +bias, tf32
        #pragma unroll
        for (int nt = 0; nt < 2; nt++) {
            const int bcol = nt * 8 + 2 * qc;
            smu[OFF_K + (ebk + qr) * SK + bcol]         = f2t(kD[nt][0] + bk0);
            smu[OFF_K + (ebk + qr) * SK + bcol + 1]     = f2t(kD[nt][1] + bk0);
            smu[OFF_K + (ebk + qr + 8) * SK + bcol]     = f2t(kD[nt][2] + bk1);
            smu[OFF_K + (ebk + qr + 8) * SK + bcol + 1] = f2t(kD[nt][3] + bk1);
            smu[OFF_V + bcol * SV + ebk + qr]           = f2t(vD[nt][0] + bv0);
            smu[OFF_V + (bcol + 1) * SV + ebk + qr]     = f2t(vD[nt][1] + bv0);
            smu[OFF_V + bcol * SV + ebk + qr + 8]       = f2t(vD[nt][2] + bv1);
            smu[OFF_V + (bcol + 1) * SV + ebk + qr + 8] = f2t(vD[nt][3] + bv1);
        }
        __syncthreads();

        // ======== phase 2: scores tile-streamed; E~ = exp(scores*scale) ========
        float s0 = 0.0f, s1 = 0.0f;
        {
            uint32_t a0[4], a1[4];
            a0[0] = smu[OFF_K + (ebk + qr) * SK + qc];
            a0[1] = smu[OFF_K + (ebk + qr + 8) * SK + qc];
            a0[2] = smu[OFF_K + (ebk + qr) * SK + qc + 4];
            a0[3] = smu[OFF_K + (ebk + qr + 8) * SK + qc + 4];
            a1[0] = smu[OFF_K + (ebk + qr) * SK + 8 + qc];
            a1[1] = smu[OFF_K + (ebk + qr + 8) * SK + 8 + qc];
            a1[2] = smu[OFF_K + (ebk + qr) * SK + 8 + qc + 4];
            a1[3] = smu[OFF_K + (ebk + qr + 8) * SK + 8 + qc + 4];
            #pragma unroll
            for (int nt = 0; nt < 16; nt++) {
                float S4[4] = {0, 0, 0, 0};
                uint32_t b[2];
                b[0] = smu[OFF_V + qc * SV + nt * 8 + qr];
                b[1] = smu[OFF_V + (qc + 4) * SV + nt * 8 + qr];
                mma8(S4, a0, b);
                b[0] = smu[OFF_V + (8 + qc) * SV + nt * 8 + qr];
                b[1] = smu[OFF_V + (8 + qc + 4) * SV + nt * 8 + qr];
                mma8(S4, a1, b);
                const float e0 = ex2f(S4[0] * C2), e1 = ex2f(S4[1] * C2);
                const float e2 = ex2f(S4[2] * C2), e3 = ex2f(S4[3] * C2);
                s0 += e0 + e1;
                s1 += e2 + e3;
                uint2 p0 = { f2t(e0), f2t(e1) };
                *reinterpret_cast<uint2*>(&smu[OFF_E + (ebk + qr) * SE + nt * 8 + 2 * qc]) = p0;
                uint2 p1 = { f2t(e2), f2t(e3) };
                *reinterpret_cast<uint2*>(&smu[OFF_E + (ebk + qr + 8) * SE + nt * 8 + 2 * qc]) = p1;
            }
        }
        // row sums over qc group -> inv to smem
        s0 += __shfl_xor_sync(0xffffffffu, s0, 1);
        s0 += __shfl_xor_sync(0xffffffffu, s0, 2);
        s1 += __shfl_xor_sync(0xffffffffu, s1, 1);
        s1 += __shfl_xor_sync(0xffffffffu, s1, 2);
        if (qc == 0) {
            sm[OFF_INV + ebk + qr]     = 1.0f / s0;
            sm[OFF_INV + ebk + qr + 8] = 1.0f / s1;
        }
        __syncthreads();

        // ======== phase 3: O = x @ E~^T, then scale cols by inv[e] ========
        float O[2][4] = {{0,0,0,0},{0,0,0,0}};
        #pragma unroll
        for (int kk = 0; kk < 16; kk++) {
            const int fb = kk * 8;
            const uint32_t a[4] = { xf[kk][0], xf[kk][2], xf[kk][1], xf[kk][3] };
            uint32_t bn0[2], bn1[2];
            bn0[0] = smu[OFF_E + (ebk + qr) * SE + fb + qc];
            bn0[1] = smu[OFF_E + (ebk + qr) * SE + fb + qc + 4];
            bn1[0] = smu[OFF_E + (ebk + 8 + qr) * SE + fb + qc];
            bn1[1] = smu[OFF_E + (ebk + 8 + qr) * SE + fb + qc + 4];
            mma8(O[0], a, bn0); mma8(O[1], a, bn1);
        }
        // write out[s][b][e]: rows b = qr / qr+8, cols e = ebk + nt*8 + 2qc
        {
            float* op = out + (size_t)s * 2048;
            #pragma unroll
            for (int nt = 0; nt < 2; nt++) {
                const int ec = ebk + nt * 8 + 2 * qc;
                const float ia = sm[OFF_INV + ec];
                const float ib = sm[OFF_INV + ec + 1];
                *reinterpret_cast<float2*>(&op[qr * 128 + ec]) =
                    make_float2(O[nt][0] * ia, O[nt][1] * ib);
                *reinterpret_cast<float2*>(&op[(qr + 8) * 128 + ec]) =
                    make_float2(O[nt][2] * ia, O[nt][3] * ib);
            }
        }
        __syncthreads();  // protect x/E/inv from next-iter overwrites
        s = snext;
    }
}

extern "C" void kernel_launch(void* const* d_in, const int* in_sizes, int n_in,
                              void* d_out, int out_size) {
    const float* x  = (const float*)d_in[0];
    const float* Wk = (const float*)d_in[1];
    const float* bk = (const float*)d_in[2];
    const float* Wv = (const float*)d_in[3];
    const float* bv = (const float*)d_in[4];
    float* out = (float*)d_out;

    int sms = 148;
    cudaDeviceGetAttribute(&sms, cudaDevAttrMultiProcessorCount, 0);
    if (sms <= 0) sms = 148;
    cudaFuncSetAttribute(nsa_mma, cudaFuncAttributeMaxDynamicSharedMemorySize, SMEM_BYTES);
    nsa_mma<<<sms, 256, SMEM_BYTES>>>(x, Wk, bk, Wv, bv, out);
}